// round 12
// baseline (speedup 1.0000x reference)
#include <cuda_runtime.h>
#include <cuda_fp16.h>
#include <cuda_bf16.h>
#include <math_constants.h>

#define NNODES   100000
#define EEDGES   1600000
#define NEG_SLOPE 0.2f
#define HEADS 4
#define SLOT_CAP 128

// ---------------------------------------------------------------------------
// Device scratch (static; no cudaMalloc allowed). .bss is zero-initialized,
// and g_deg is returned to zero by the last consumer each launch.
// ---------------------------------------------------------------------------
__device__ uint4 g_xlh_raw[NNODES * 256 * 2 / 16];  // xl as fp16
__device__ uint4 g_xrh_raw[NNODES * 256 * 2 / 16];  // xr as fp16
__device__ float g_h [NNODES * 64];
__device__ int   g_slots[NNODES * SLOT_CAP];        // src ids grouped by dst
__device__ int   g_deg [NNODES];                    // per-dst degree (self loop incl.)

static inline int cdiv(int a, int b) { return (a + b - 1) / b; }

// ---------------------------------------------------------------------------
// Edge-index dtype check (int64 vs int32)
// ---------------------------------------------------------------------------
__device__ __forceinline__ bool ei_is64(const void* ei, int Nn) {
    const long long* p = (const long long*)ei;
    bool ok = true;
    #pragma unroll
    for (int i = 0; i < 4; i++) {
        long long v = __ldg(p + i);
        ok = ok && (v >= 0 && v < (long long)Nn);
    }
    return ok;
}

// ---------------------------------------------------------------------------
// ONE-kernel edge grouping (R11-proven)
// ---------------------------------------------------------------------------
__global__ void fill_kernel(const void* ei, int E, int Nn) {
    int i = blockIdx.x * blockDim.x + threadIdx.x;
    if (i >= E + Nn) return;
    int s, d;
    if (i < E) {
        if (ei_is64(ei, Nn)) {
            const long long* p = (const long long*)ei;
            s = (int)__ldg(p + i); d = (int)__ldg(p + E + i);
        } else {
            const int* p = (const int*)ei;
            s = __ldg(p + i); d = __ldg(p + E + i);
        }
    } else {
        s = d = i - E;
    }
    int pos = atomicAdd(&g_deg[d], 1);
    if (pos < SLOT_CAP)
        g_slots[d * SLOT_CAP + pos] = s;
}

// ---------------------------------------------------------------------------
// bf16 m16n8k16 mma + ldmatrix
// ---------------------------------------------------------------------------
__device__ __forceinline__ void mma_bf16(float* d, const unsigned* a, const unsigned* b) {
    asm volatile(
        "mma.sync.aligned.m16n8k16.row.col.f32.bf16.bf16.f32 "
        "{%0,%1,%2,%3}, {%4,%5,%6,%7}, {%8,%9}, {%0,%1,%2,%3};\n"
        : "+f"(d[0]), "+f"(d[1]), "+f"(d[2]), "+f"(d[3])
        : "r"(a[0]), "r"(a[1]), "r"(a[2]), "r"(a[3]),
          "r"(b[0]), "r"(b[1]));
}

__device__ __forceinline__ void ldsm_x4(unsigned* r, unsigned saddr) {
    asm volatile(
        "ldmatrix.sync.aligned.m8n8.x4.shared.b16 {%0,%1,%2,%3}, [%4];"
        : "=r"(r[0]), "=r"(r[1]), "=r"(r[2]), "=r"(r[3]) : "r"(saddr));
}

// ---------------------------------------------------------------------------
// Dual GEMM, 3x-split bf16 tensor cores, ldmatrix fragment loads.
// 128 threads (4 warps), BM=128, BN=64, warp tile m=32 x n=64, K=64.
// smem (bf16, pitch 72): As_hi[128], As_lo[128], Bs_hi[64], Bs_lo[64].
// Both outputs fp16. Grid x: [0, 2*Nc/64) -> first half Wl/Cl, rest Wr/Cr.
// ---------------------------------------------------------------------------
#define AP 72
__global__ __launch_bounds__(128)
void dual_gemm_bf16(const float* __restrict__ A,
                    const float* __restrict__ Wl, const float* __restrict__ bl,
                    const float* __restrict__ Wr, const float* __restrict__ br,
                    __half* __restrict__ Cl, __half* __restrict__ Cr,
                    int M, int Nc) {
    extern __shared__ __nv_bfloat16 smb[];
    __nv_bfloat16* As_hi = smb;
    __nv_bfloat16* As_lo = smb + 128 * AP;
    __nv_bfloat16* Bs_hi = smb + 256 * AP;
    __nv_bfloat16* Bs_lo = smb + 320 * AP;

    const int tid  = threadIdx.x;
    const int warp = tid >> 5, lane = tid & 31;
    const int g = lane >> 2, c = lane & 3;
    const int row0 = blockIdx.y * 128;
    const int col0 = blockIdx.x * 64;

    const bool isL = (col0 < Nc);
    const float* W    = isL ? Wl : Wr;
    const float* bias = isL ? bl : br;
    __half* C = isL ? Cl : Cr;
    const int cofs = isL ? col0 : col0 - Nc;

    // A tile: 128 rows x 64 cols, split to bf16 hi/lo (16 float4 per thread)
    #pragma unroll
    for (int i = 0; i < 16; i++) {
        int idx = tid + i * 128;
        int r = idx >> 4, c4 = (idx & 15) << 2;
        int row = row0 + r;
        float4 v = make_float4(0.f, 0.f, 0.f, 0.f);
        if (row < M)
            v = *reinterpret_cast<const float4*>(A + (size_t)row * 64 + c4);
        float vv[4] = {v.x, v.y, v.z, v.w};
        __nv_bfloat16 hi[4], lo[4];
        #pragma unroll
        for (int j = 0; j < 4; j++) {
            hi[j] = __float2bfloat16_rn(vv[j]);
            lo[j] = __float2bfloat16_rn(vv[j] - __bfloat162float(hi[j]));
        }
        __nv_bfloat162* dh = reinterpret_cast<__nv_bfloat162*>(&As_hi[r * AP + c4]);
        __nv_bfloat162* dl = reinterpret_cast<__nv_bfloat162*>(&As_lo[r * AP + c4]);
        dh[0] = __nv_bfloat162{hi[0], hi[1]}; dh[1] = __nv_bfloat162{hi[2], hi[3]};
        dl[0] = __nv_bfloat162{lo[0], lo[1]}; dl[1] = __nv_bfloat162{lo[2], lo[3]};
    }
    // B tile: W[k][cofs..] -> Bs[n][k] transposed, split hi/lo (8 float4/thread)
    #pragma unroll
    for (int i = 0; i < 8; i++) {
        int idx = tid + i * 128;
        int k = idx >> 4, c4 = (idx & 15) << 2;
        float4 v = *reinterpret_cast<const float4*>(W + (size_t)k * Nc + cofs + c4);
        float vv[4] = {v.x, v.y, v.z, v.w};
        #pragma unroll
        for (int j = 0; j < 4; j++) {
            __nv_bfloat16 hi = __float2bfloat16_rn(vv[j]);
            Bs_hi[(c4 + j) * AP + k] = hi;
            Bs_lo[(c4 + j) * AP + k] = __float2bfloat16_rn(vv[j] - __bfloat162float(hi));
        }
    }
    __syncthreads();

    float acc[2][8][4];
    #pragma unroll
    for (int mt = 0; mt < 2; mt++)
        #pragma unroll
        for (int n = 0; n < 8; n++)
            #pragma unroll
            for (int j = 0; j < 4; j++) acc[mt][n][j] = 0.f;

    const int wr = warp * 32;
    // per-lane ldmatrix row pointers (lane -> tile row mapping)
    const int a_i    = lane >> 3;                 // tile index 0..3
    const int a_rsub = ((a_i & 1) << 3) + (lane & 7);
    const int a_koff = (a_i >> 1) << 3;
    const int b_rsub = ((lane >> 4) << 3) + (lane & 7);
    const int b_koff = ((lane >> 3) & 1) << 3;

    #pragma unroll
    for (int kk = 0; kk < 4; kk++) {
        const int k0 = kk * 16;
        unsigned ahi[2][4], alo[2][4];
        #pragma unroll
        for (int mt = 0; mt < 2; mt++) {
            int row = wr + mt * 16 + a_rsub;
            unsigned sh = (unsigned)__cvta_generic_to_shared(&As_hi[row * AP + k0 + a_koff]);
            unsigned sl = (unsigned)__cvta_generic_to_shared(&As_lo[row * AP + k0 + a_koff]);
            ldsm_x4(ahi[mt], sh);
            ldsm_x4(alo[mt], sl);
        }
        #pragma unroll
        for (int np = 0; np < 4; np++) {          // n-pairs: 2 n8-tiles each
            int nrow = np * 16 + b_rsub;
            unsigned sh = (unsigned)__cvta_generic_to_shared(&Bs_hi[nrow * AP + k0 + b_koff]);
            unsigned sl = (unsigned)__cvta_generic_to_shared(&Bs_lo[nrow * AP + k0 + b_koff]);
            unsigned bh4[4], bl4[4];
            ldsm_x4(bh4, sh);
            ldsm_x4(bl4, sl);
            #pragma unroll
            for (int sub = 0; sub < 2; sub++) {
                int n = np * 2 + sub;
                unsigned bhi[2] = {bh4[2 * sub], bh4[2 * sub + 1]};
                unsigned blo[2] = {bl4[2 * sub], bl4[2 * sub + 1]};
                #pragma unroll
                for (int mt = 0; mt < 2; mt++) {
                    mma_bf16(acc[mt][n], ahi[mt], bhi);
                    mma_bf16(acc[mt][n], alo[mt], bhi);
                    mma_bf16(acc[mt][n], ahi[mt], blo);
                }
            }
        }
    }

    #pragma unroll
    for (int mt = 0; mt < 2; mt++) {
        #pragma unroll
        for (int n = 0; n < 8; n++) {
            int colg = cofs + n * 8 + 2 * c;
            float bx = __ldg(bias + colg);
            float by = __ldg(bias + colg + 1);
            int r1 = row0 + wr + mt * 16 + g, r2 = r1 + 8;
            if (r1 < M)
                *reinterpret_cast<__half2*>(C + (size_t)r1 * Nc + colg) =
                    __floats2half2_rn(acc[mt][n][0] + bx, acc[mt][n][1] + by);
            if (r2 < M)
                *reinterpret_cast<__half2*>(C + (size_t)r2 * Nc + colg) =
                    __floats2half2_rn(acc[mt][n][2] + bx, acc[mt][n][3] + by);
        }
    }
}

// ---------------------------------------------------------------------------
// fp16 vector load
// ---------------------------------------------------------------------------
template<int PE>
__device__ __forceinline__ void loadVecH(const __half* __restrict__ p, float* v) {
    if constexpr (PE == 8) {
        uint4 t = __ldg(reinterpret_cast<const uint4*>(p));
        float2 f;
        f = __half22float2(*reinterpret_cast<__half2*>(&t.x)); v[0] = f.x; v[1] = f.y;
        f = __half22float2(*reinterpret_cast<__half2*>(&t.y)); v[2] = f.x; v[3] = f.y;
        f = __half22float2(*reinterpret_cast<__half2*>(&t.z)); v[4] = f.x; v[5] = f.y;
        f = __half22float2(*reinterpret_cast<__half2*>(&t.w)); v[6] = f.x; v[7] = f.y;
    } else {
        unsigned t = __ldg(reinterpret_cast<const unsigned*>(p));
        float2 f = __half22float2(*reinterpret_cast<__half2*>(&t));
        v[0] = f.x; v[1] = f.y;
    }
}

// ---------------------------------------------------------------------------
// Fused GATv2 edge pass (R11-proven): warp per dst node, slot segments,
// no-max softmax + lrelu-identity dot, xl/xr fp16, math fp32.
// MEAN kernel re-zeros g_deg[w] for the next graph replay.
// ---------------------------------------------------------------------------
template<int CC, bool MEAN>
__global__ void fused_gat_kernel(const float* __restrict__ att,
                                 const float* __restrict__ bo,
                                 float* __restrict__ outp, int Nn) {
    constexpr int D = HEADS * CC;
    constexpr int PE = D / 32;
    int w = (blockIdx.x * blockDim.x + threadIdx.x) >> 5;
    int lane = threadIdx.x & 31;
    if (w >= Nn) return;

    const __half* xlh = reinterpret_cast<const __half*>(g_xlh_raw);
    const __half* xrh = reinterpret_cast<const __half*>(g_xrh_raw);
    const int f0 = lane * PE;

    int deg = g_deg[w];
    int cnt = (deg < SLOT_CAP) ? deg : SLOT_CAP;
    const int* seg = g_slots + (size_t)w * SLOT_CAP;

    float vr[PE], av6[PE], av4[PE];
    loadVecH<PE>(xrh + (size_t)w * D + f0, vr);
    #pragma unroll
    for (int j = 0; j < PE; j++) {
        float a = __ldg(att + f0 + j);
        av6[j] = (0.5f + 0.5f * NEG_SLOPE) * a;
        av4[j] = (0.5f - 0.5f * NEG_SLOPE) * a;
    }

    float l = 0.f;
    float acc[PE];
    #pragma unroll
    for (int j = 0; j < PE; j++) acc[j] = 0.f;

    float vl[PE];
    {
        int s0 = __ldg(seg);
        loadVecH<PE>(xlh + (size_t)s0 * D + f0, vl);
    }

    for (int p = 0; p < cnt; p++) {
        float cvl[PE];
        #pragma unroll
        for (int j = 0; j < PE; j++) cvl[j] = vl[j];
        if (p + 1 < cnt) {
            int sn = __ldg(seg + p + 1);
            loadVecH<PE>(xlh + (size_t)sn * D + f0, vl);
        }
        float partial = 0.f;
        #pragma unroll
        for (int j = 0; j < PE; j++) {
            float v = cvl[j] + vr[j];
            partial = fmaf(av6[j], v, partial);
            partial = fmaf(av4[j], fabsf(v), partial);
        }
        #pragma unroll
        for (int off = 4; off; off >>= 1)
            partial += __shfl_xor_sync(0xffffffffu, partial, off);

        float pe = __expf(partial);
        l += pe;
        #pragma unroll
        for (int j = 0; j < PE; j++)
            acc[j] = fmaf(pe, cvl[j], acc[j]);
    }

    if constexpr (MEAN) {
        if (lane == 0) g_deg[w] = 0;
    }

    float inv = 1.f / (l + 1e-16f);

    if constexpr (!MEAN) {
        float2 o;
        o.x = acc[0] * inv + __ldg(bo + f0 + 0);
        o.y = acc[1] * inv + __ldg(bo + f0 + 1);
        o.x = (o.x > 0.f) ? o.x : 0.f;
        o.y = (o.y > 0.f) ? o.y : 0.f;
        *reinterpret_cast<float2*>(outp + (size_t)w * D + f0) = o;
    } else {
        #pragma unroll
        for (int j = 0; j < PE; j++) acc[j] *= inv;
        #pragma unroll
        for (int j = 0; j < PE; j++) {
            acc[j] += __shfl_xor_sync(0xffffffffu, acc[j], 8);
            acc[j] += __shfl_xor_sync(0xffffffffu, acc[j], 16);
        }
        if (lane < 8) {
            float o[PE];
            #pragma unroll
            for (int j = 0; j < PE; j++) {
                float v = 0.25f * acc[j] + __ldg(bo + f0 + j);
                o[j] = (v > 0.f) ? v : 0.f;
            }
            #pragma unroll
            for (int j = 0; j < PE / 4; j++)
                *reinterpret_cast<float4*>(outp + (size_t)w * 64 + f0 + j * 4) =
                    make_float4(o[j*4], o[j*4+1], o[j*4+2], o[j*4+3]);
        }
    }
}

// ---------------------------------------------------------------------------
// Host launcher — 5 kernels total
// ---------------------------------------------------------------------------
extern "C" void kernel_launch(void* const* d_in, const int* in_sizes, int n_in,
                              void* d_out, int out_size) {
    const float* x   = (const float*)d_in[0];
    const void*  ei  = d_in[1];
    const float* Wl1 = (const float*)d_in[3];
    const float* bl1 = (const float*)d_in[4];
    const float* Wr1 = (const float*)d_in[5];
    const float* br1 = (const float*)d_in[6];
    const float* att1= (const float*)d_in[7];
    const float* bo1 = (const float*)d_in[8];
    const float* Wl2 = (const float*)d_in[9];
    const float* bl2 = (const float*)d_in[10];
    const float* Wr2 = (const float*)d_in[11];
    const float* br2 = (const float*)d_in[12];
    const float* att2= (const float*)d_in[13];
    const float* bo2 = (const float*)d_in[14];
    float* out = (float*)d_out;

    const int N = in_sizes[0] / 64;
    const int E = in_sizes[1] / 2;

    __half* p_xlh; __half* p_xrh; float* p_h;
    cudaGetSymbolAddress((void**)&p_xlh, g_xlh_raw);
    cudaGetSymbolAddress((void**)&p_xrh, g_xrh_raw);
    cudaGetSymbolAddress((void**)&p_h,   g_h);

    const int TB = 256;
    const int SMEM_GEMM = 384 * AP * 2;   // 55296 B
    static int attrSet = 0;
    if (!attrSet) {
        cudaFuncSetAttribute(dual_gemm_bf16,
                             cudaFuncAttributeMaxDynamicSharedMemorySize, SMEM_GEMM);
        attrSet = 1;
    }

    int fusedBlocks = cdiv(N, TB / 32);

    // ---- edge grouping ----
    fill_kernel<<<cdiv(E + N, TB), TB>>>(ei, E, N);

    // ---- layer 1: dual GEMM (Nc=64) + fused GAT ----
    dim3 g1(2, cdiv(N, 128));
    dual_gemm_bf16<<<g1, 128, SMEM_GEMM>>>(x, Wl1, bl1, Wr1, br1, p_xlh, p_xrh, N, 64);
    fused_gat_kernel<16, false><<<fusedBlocks, TB>>>(att1, bo1, p_h, N);

    // ---- layer 2: dual GEMM (Nc=256) + fused GAT (zeros g_deg) ----
    dim3 g2(8, cdiv(N, 128));
    dual_gemm_bf16<<<g2, 128, SMEM_GEMM>>>(p_h, Wl2, bl2, Wr2, br2, p_xlh, p_xrh, N, 256);
    fused_gat_kernel<64, true><<<fusedBlocks, TB>>>(att2, bo2, out, N);
}

// round 14
// speedup vs baseline: 1.4132x; 1.4132x over previous
#include <cuda_runtime.h>
#include <cuda_fp16.h>
#include <cuda_bf16.h>
#include <math_constants.h>

#define NNODES   100000
#define EEDGES   1600000
#define NEG_SLOPE 0.2f
#define HEADS 4
#define SLOT_CAP 128

// ---------------------------------------------------------------------------
// Device scratch (static; no cudaMalloc allowed). .bss is zero-initialized,
// and g_deg is returned to zero by the last consumer each launch.
// ---------------------------------------------------------------------------
__device__ uint4 g_xlh_raw[NNODES * 256 * 2 / 16];  // xl as fp16
__device__ uint4 g_xrh_raw[NNODES * 256 * 2 / 16];  // xr as fp16
__device__ float g_h [NNODES * 64];
__device__ int   g_slots[NNODES * SLOT_CAP];        // src ids grouped by dst
__device__ int   g_deg [NNODES];                    // per-dst degree (self loop incl.)

static inline int cdiv(int a, int b) { return (a + b - 1) / b; }

// ---------------------------------------------------------------------------
// Edge-index dtype check (int64 vs int32)
// ---------------------------------------------------------------------------
__device__ __forceinline__ bool ei_is64(const void* ei, int Nn) {
    const long long* p = (const long long*)ei;
    bool ok = true;
    #pragma unroll
    for (int i = 0; i < 4; i++) {
        long long v = __ldg(p + i);
        ok = ok && (v >= 0 && v < (long long)Nn);
    }
    return ok;
}

// ---------------------------------------------------------------------------
// ONE-kernel edge grouping (R11-proven)
// ---------------------------------------------------------------------------
__global__ void fill_kernel(const void* ei, int E, int Nn) {
    int i = blockIdx.x * blockDim.x + threadIdx.x;
    if (i >= E + Nn) return;
    int s, d;
    if (i < E) {
        if (ei_is64(ei, Nn)) {
            const long long* p = (const long long*)ei;
            s = (int)__ldg(p + i); d = (int)__ldg(p + E + i);
        } else {
            const int* p = (const int*)ei;
            s = __ldg(p + i); d = __ldg(p + E + i);
        }
    } else {
        s = d = i - E;
    }
    int pos = atomicAdd(&g_deg[d], 1);
    if (pos < SLOT_CAP)
        g_slots[d * SLOT_CAP + pos] = s;
}

// ---------------------------------------------------------------------------
// bf16 m16n8k16 mma + ldmatrix
// ---------------------------------------------------------------------------
__device__ __forceinline__ void mma_bf16(float* d, const unsigned* a, const unsigned* b) {
    asm volatile(
        "mma.sync.aligned.m16n8k16.row.col.f32.bf16.bf16.f32 "
        "{%0,%1,%2,%3}, {%4,%5,%6,%7}, {%8,%9}, {%0,%1,%2,%3};\n"
        : "+f"(d[0]), "+f"(d[1]), "+f"(d[2]), "+f"(d[3])
        : "r"(a[0]), "r"(a[1]), "r"(a[2]), "r"(a[3]),
          "r"(b[0]), "r"(b[1]));
}

__device__ __forceinline__ void ldsm_x4(unsigned* r, unsigned saddr) {
    asm volatile(
        "ldmatrix.sync.aligned.m8n8.x4.shared.b16 {%0,%1,%2,%3}, [%4];"
        : "=r"(r[0]), "=r"(r[1]), "=r"(r[2]), "=r"(r[3]) : "r"(saddr));
}

// ---------------------------------------------------------------------------
// Dual GEMM, 3x-split bf16 tensor cores, ldmatrix fragment loads.
// 256 threads (8 warps), BM=128, BN=64, warp tile m=16 x n=64, K=64
// (R8/R11-proven geometry + occupancy; only the fragment-load path changed).
// smem (bf16, pitch 72 halfs = 144B, 16B-aligned rows; row bank stride 4 ->
// ldmatrix 8-row phases hit all 32 banks, conflict-free — validated in R12).
// ---------------------------------------------------------------------------
#define AP 72
__global__ __launch_bounds__(256)
void dual_gemm_bf16(const float* __restrict__ A,
                    const float* __restrict__ Wl, const float* __restrict__ bl,
                    const float* __restrict__ Wr, const float* __restrict__ br,
                    __half* __restrict__ Cl, __half* __restrict__ Cr,
                    int M, int Nc) {
    extern __shared__ __nv_bfloat16 smb[];
    __nv_bfloat16* As_hi = smb;
    __nv_bfloat16* As_lo = smb + 128 * AP;
    __nv_bfloat16* Bs_hi = smb + 256 * AP;
    __nv_bfloat16* Bs_lo = smb + 320 * AP;

    const int tid  = threadIdx.x;
    const int warp = tid >> 5, lane = tid & 31;
    const int g = lane >> 2, c = lane & 3;
    const int row0 = blockIdx.y * 128;
    const int col0 = blockIdx.x * 64;

    const bool isL = (col0 < Nc);
    const float* W    = isL ? Wl : Wr;
    const float* bias = isL ? bl : br;
    __half* C = isL ? Cl : Cr;
    const int cofs = isL ? col0 : col0 - Nc;

    // A tile: 128 rows x 64 cols, split to bf16 hi/lo, packed 32-bit stores
    #pragma unroll
    for (int i = 0; i < 8; i++) {
        int idx = tid + i * 256;
        int r = idx >> 4, c4 = (idx & 15) << 2;
        int row = row0 + r;
        float4 v = make_float4(0.f, 0.f, 0.f, 0.f);
        if (row < M)
            v = *reinterpret_cast<const float4*>(A + (size_t)row * 64 + c4);
        float vv[4] = {v.x, v.y, v.z, v.w};
        __nv_bfloat16 hi[4], lo[4];
        #pragma unroll
        for (int j = 0; j < 4; j++) {
            hi[j] = __float2bfloat16_rn(vv[j]);
            lo[j] = __float2bfloat16_rn(vv[j] - __bfloat162float(hi[j]));
        }
        __nv_bfloat162* dh = reinterpret_cast<__nv_bfloat162*>(&As_hi[r * AP + c4]);
        __nv_bfloat162* dl = reinterpret_cast<__nv_bfloat162*>(&As_lo[r * AP + c4]);
        dh[0] = __nv_bfloat162{hi[0], hi[1]}; dh[1] = __nv_bfloat162{hi[2], hi[3]};
        dl[0] = __nv_bfloat162{lo[0], lo[1]}; dl[1] = __nv_bfloat162{lo[2], lo[3]};
    }
    // B tile: W[k][cofs..] -> Bs[n][k] transposed, split hi/lo
    #pragma unroll
    for (int i = 0; i < 4; i++) {
        int idx = tid + i * 256;
        int k = idx >> 4, c4 = (idx & 15) << 2;
        float4 v = *reinterpret_cast<const float4*>(W + (size_t)k * Nc + cofs + c4);
        float vv[4] = {v.x, v.y, v.z, v.w};
        #pragma unroll
        for (int j = 0; j < 4; j++) {
            __nv_bfloat16 hi = __float2bfloat16_rn(vv[j]);
            Bs_hi[(c4 + j) * AP + k] = hi;
            Bs_lo[(c4 + j) * AP + k] = __float2bfloat16_rn(vv[j] - __bfloat162float(hi));
        }
    }
    __syncthreads();

    float acc[8][4];
    #pragma unroll
    for (int n = 0; n < 8; n++)
        #pragma unroll
        for (int j = 0; j < 4; j++) acc[n][j] = 0.f;

    const int wr = warp * 16;
    // ldmatrix lane->row mappings (validated by R12 correctness)
    const int a_rsub = (((lane >> 3) & 1) << 3) + (lane & 7);   // m16k16 x4
    const int a_koff = (lane >> 4) << 3;
    const int b_rsub = ((lane >> 4) << 3) + (lane & 7);          // n16k16 x4
    const int b_koff = ((lane >> 3) & 1) << 3;

    #pragma unroll
    for (int kk = 0; kk < 4; kk++) {
        const int k0 = kk * 16;
        unsigned ahi[4], alo[4];
        {
            int row = wr + a_rsub;
            unsigned sh = (unsigned)__cvta_generic_to_shared(&As_hi[row * AP + k0 + a_koff]);
            unsigned sl = (unsigned)__cvta_generic_to_shared(&As_lo[row * AP + k0 + a_koff]);
            ldsm_x4(ahi, sh);
            ldsm_x4(alo, sl);
        }
        #pragma unroll
        for (int np = 0; np < 4; np++) {          // 4 n-pairs, 2 n8-tiles each
            int nrow = np * 16 + b_rsub;
            unsigned sh = (unsigned)__cvta_generic_to_shared(&Bs_hi[nrow * AP + k0 + b_koff]);
            unsigned sl = (unsigned)__cvta_generic_to_shared(&Bs_lo[nrow * AP + k0 + b_koff]);
            unsigned bh4[4], bl4[4];
            ldsm_x4(bh4, sh);
            ldsm_x4(bl4, sl);
            #pragma unroll
            for (int sub = 0; sub < 2; sub++) {
                int n = np * 2 + sub;
                unsigned bhi[2] = {bh4[2 * sub], bh4[2 * sub + 1]};
                unsigned blo[2] = {bl4[2 * sub], bl4[2 * sub + 1]};
                mma_bf16(acc[n], ahi, bhi);
                mma_bf16(acc[n], alo, bhi);
                mma_bf16(acc[n], ahi, blo);
            }
        }
    }

    #pragma unroll
    for (int n = 0; n < 8; n++) {
        int colg = cofs + n * 8 + 2 * c;
        float bx = __ldg(bias + colg);
        float by = __ldg(bias + colg + 1);
        int r1 = row0 + wr + g, r2 = r1 + 8;
        if (r1 < M)
            *reinterpret_cast<__half2*>(C + (size_t)r1 * Nc + colg) =
                __floats2half2_rn(acc[n][0] + bx, acc[n][1] + by);
        if (r2 < M)
            *reinterpret_cast<__half2*>(C + (size_t)r2 * Nc + colg) =
                __floats2half2_rn(acc[n][2] + bx, acc[n][3] + by);
    }
}

// ---------------------------------------------------------------------------
// fp16 vector load
// ---------------------------------------------------------------------------
template<int PE>
__device__ __forceinline__ void loadVecH(const __half* __restrict__ p, float* v) {
    if constexpr (PE == 8) {
        uint4 t = __ldg(reinterpret_cast<const uint4*>(p));
        float2 f;
        f = __half22float2(*reinterpret_cast<__half2*>(&t.x)); v[0] = f.x; v[1] = f.y;
        f = __half22float2(*reinterpret_cast<__half2*>(&t.y)); v[2] = f.x; v[3] = f.y;
        f = __half22float2(*reinterpret_cast<__half2*>(&t.z)); v[4] = f.x; v[5] = f.y;
        f = __half22float2(*reinterpret_cast<__half2*>(&t.w)); v[6] = f.x; v[7] = f.y;
    } else {
        unsigned t = __ldg(reinterpret_cast<const unsigned*>(p));
        float2 f = __half22float2(*reinterpret_cast<__half2*>(&t));
        v[0] = f.x; v[1] = f.y;
    }
}

// ---------------------------------------------------------------------------
// Fused GATv2 edge pass (R11-proven): warp per dst node, slot segments,
// no-max softmax + lrelu-identity dot, xl/xr fp16, math fp32.
// MEAN kernel re-zeros g_deg[w] for the next graph replay.
// ---------------------------------------------------------------------------
template<int CC, bool MEAN>
__global__ void fused_gat_kernel(const float* __restrict__ att,
                                 const float* __restrict__ bo,
                                 float* __restrict__ outp, int Nn) {
    constexpr int D = HEADS * CC;
    constexpr int PE = D / 32;
    int w = (blockIdx.x * blockDim.x + threadIdx.x) >> 5;
    int lane = threadIdx.x & 31;
    if (w >= Nn) return;

    const __half* xlh = reinterpret_cast<const __half*>(g_xlh_raw);
    const __half* xrh = reinterpret_cast<const __half*>(g_xrh_raw);
    const int f0 = lane * PE;

    int deg = g_deg[w];
    int cnt = (deg < SLOT_CAP) ? deg : SLOT_CAP;
    const int* seg = g_slots + (size_t)w * SLOT_CAP;

    float vr[PE], av6[PE], av4[PE];
    loadVecH<PE>(xrh + (size_t)w * D + f0, vr);
    #pragma unroll
    for (int j = 0; j < PE; j++) {
        float a = __ldg(att + f0 + j);
        av6[j] = (0.5f + 0.5f * NEG_SLOPE) * a;
        av4[j] = (0.5f - 0.5f * NEG_SLOPE) * a;
    }

    float l = 0.f;
    float acc[PE];
    #pragma unroll
    for (int j = 0; j < PE; j++) acc[j] = 0.f;

    float vl[PE];
    {
        int s0 = __ldg(seg);
        loadVecH<PE>(xlh + (size_t)s0 * D + f0, vl);
    }

    for (int p = 0; p < cnt; p++) {
        float cvl[PE];
        #pragma unroll
        for (int j = 0; j < PE; j++) cvl[j] = vl[j];
        if (p + 1 < cnt) {
            int sn = __ldg(seg + p + 1);
            loadVecH<PE>(xlh + (size_t)sn * D + f0, vl);
        }
        float partial = 0.f;
        #pragma unroll
        for (int j = 0; j < PE; j++) {
            float v = cvl[j] + vr[j];
            partial = fmaf(av6[j], v, partial);
            partial = fmaf(av4[j], fabsf(v), partial);
        }
        #pragma unroll
        for (int off = 4; off; off >>= 1)
            partial += __shfl_xor_sync(0xffffffffu, partial, off);

        float pe = __expf(partial);
        l += pe;
        #pragma unroll
        for (int j = 0; j < PE; j++)
            acc[j] = fmaf(pe, cvl[j], acc[j]);
    }

    if constexpr (MEAN) {
        if (lane == 0) g_deg[w] = 0;
    }

    float inv = 1.f / (l + 1e-16f);

    if constexpr (!MEAN) {
        float2 o;
        o.x = acc[0] * inv + __ldg(bo + f0 + 0);
        o.y = acc[1] * inv + __ldg(bo + f0 + 1);
        o.x = (o.x > 0.f) ? o.x : 0.f;
        o.y = (o.y > 0.f) ? o.y : 0.f;
        *reinterpret_cast<float2*>(outp + (size_t)w * D + f0) = o;
    } else {
        #pragma unroll
        for (int j = 0; j < PE; j++) acc[j] *= inv;
        #pragma unroll
        for (int j = 0; j < PE; j++) {
            acc[j] += __shfl_xor_sync(0xffffffffu, acc[j], 8);
            acc[j] += __shfl_xor_sync(0xffffffffu, acc[j], 16);
        }
        if (lane < 8) {
            float o[PE];
            #pragma unroll
            for (int j = 0; j < PE; j++) {
                float v = 0.25f * acc[j] + __ldg(bo + f0 + j);
                o[j] = (v > 0.f) ? v : 0.f;
            }
            #pragma unroll
            for (int j = 0; j < PE / 4; j++)
                *reinterpret_cast<float4*>(outp + (size_t)w * 64 + f0 + j * 4) =
                    make_float4(o[j*4], o[j*4+1], o[j*4+2], o[j*4+3]);
        }
    }
}

// ---------------------------------------------------------------------------
// Host launcher — 5 kernels total
// ---------------------------------------------------------------------------
extern "C" void kernel_launch(void* const* d_in, const int* in_sizes, int n_in,
                              void* d_out, int out_size) {
    const float* x   = (const float*)d_in[0];
    const void*  ei  = d_in[1];
    const float* Wl1 = (const float*)d_in[3];
    const float* bl1 = (const float*)d_in[4];
    const float* Wr1 = (const float*)d_in[5];
    const float* br1 = (const float*)d_in[6];
    const float* att1= (const float*)d_in[7];
    const float* bo1 = (const float*)d_in[8];
    const float* Wl2 = (const float*)d_in[9];
    const float* bl2 = (const float*)d_in[10];
    const float* Wr2 = (const float*)d_in[11];
    const float* br2 = (const float*)d_in[12];
    const float* att2= (const float*)d_in[13];
    const float* bo2 = (const float*)d_in[14];
    float* out = (float*)d_out;

    const int N = in_sizes[0] / 64;
    const int E = in_sizes[1] / 2;

    __half* p_xlh; __half* p_xrh; float* p_h;
    cudaGetSymbolAddress((void**)&p_xlh, g_xlh_raw);
    cudaGetSymbolAddress((void**)&p_xrh, g_xrh_raw);
    cudaGetSymbolAddress((void**)&p_h,   g_h);

    const int TB = 256;
    const int SMEM_GEMM = 384 * AP * 2;   // 55296 B
    static int attrSet = 0;
    if (!attrSet) {
        cudaFuncSetAttribute(dual_gemm_bf16,
                             cudaFuncAttributeMaxDynamicSharedMemorySize, SMEM_GEMM);
        attrSet = 1;
    }

    int fusedBlocks = cdiv(N, TB / 32);

    // ---- edge grouping ----
    fill_kernel<<<cdiv(E + N, TB), TB>>>(ei, E, N);

    // ---- layer 1: dual GEMM (Nc=64) + fused GAT ----
    dim3 g1(2, cdiv(N, 128));
    dual_gemm_bf16<<<g1, TB, SMEM_GEMM>>>(x, Wl1, bl1, Wr1, br1, p_xlh, p_xrh, N, 64);
    fused_gat_kernel<16, false><<<fusedBlocks, TB>>>(att1, bo1, p_h, N);

    // ---- layer 2: dual GEMM (Nc=256) + fused GAT (zeros g_deg) ----
    dim3 g2(8, cdiv(N, 128));
    dual_gemm_bf16<<<g2, TB, SMEM_GEMM>>>(p_h, Wl2, bl2, Wr2, br2, p_xlh, p_xrh, N, 256);
    fused_gat_kernel<64, true><<<fusedBlocks, TB>>>(att2, bo2, out, N);
}

// round 15
// speedup vs baseline: 1.6214x; 1.1473x over previous
#include <cuda_runtime.h>
#include <cuda_fp16.h>
#include <cuda_bf16.h>
#include <math_constants.h>

#define NNODES   100000
#define EEDGES   1600000
#define NEG_SLOPE 0.2f
#define HEADS 4
#define SLOT_CAP 128

// ---------------------------------------------------------------------------
// Device scratch (static; no cudaMalloc allowed). .bss is zero-initialized,
// and g_deg is returned to zero by the last consumer each launch.
// ---------------------------------------------------------------------------
__device__ uint4 g_xlh_raw[NNODES * 256 * 2 / 16];  // xl as fp16
__device__ uint4 g_xrh_raw[NNODES * 256 * 2 / 16];  // xr as fp16
__device__ float g_h [NNODES * 64];
__device__ int   g_slots[NNODES * SLOT_CAP];        // src ids grouped by dst
__device__ int   g_deg [NNODES];                    // per-dst degree (self loop incl.)

static inline int cdiv(int a, int b) { return (a + b - 1) / b; }

// ---------------------------------------------------------------------------
// Edge-index dtype check (int64 vs int32)
// ---------------------------------------------------------------------------
__device__ __forceinline__ bool ei_is64(const void* ei, int Nn) {
    const long long* p = (const long long*)ei;
    bool ok = true;
    #pragma unroll
    for (int i = 0; i < 4; i++) {
        long long v = __ldg(p + i);
        ok = ok && (v >= 0 && v < (long long)Nn);
    }
    return ok;
}

// ---------------------------------------------------------------------------
// ONE-kernel edge grouping (proven)
// ---------------------------------------------------------------------------
__global__ void fill_kernel(const void* ei, int E, int Nn) {
    int i = blockIdx.x * blockDim.x + threadIdx.x;
    if (i >= E + Nn) return;
    int s, d;
    if (i < E) {
        if (ei_is64(ei, Nn)) {
            const long long* p = (const long long*)ei;
            s = (int)__ldg(p + i); d = (int)__ldg(p + E + i);
        } else {
            const int* p = (const int*)ei;
            s = __ldg(p + i); d = __ldg(p + E + i);
        }
    } else {
        s = d = i - E;
    }
    int pos = atomicAdd(&g_deg[d], 1);
    if (pos < SLOT_CAP)
        g_slots[d * SLOT_CAP + pos] = s;
}

// ---------------------------------------------------------------------------
// fp16 m16n8k16 mma + ldmatrix
// ---------------------------------------------------------------------------
__device__ __forceinline__ void mma_fp16(float* d, const unsigned* a, const unsigned* b) {
    asm volatile(
        "mma.sync.aligned.m16n8k16.row.col.f32.f16.f16.f32 "
        "{%0,%1,%2,%3}, {%4,%5,%6,%7}, {%8,%9}, {%0,%1,%2,%3};\n"
        : "+f"(d[0]), "+f"(d[1]), "+f"(d[2]), "+f"(d[3])
        : "r"(a[0]), "r"(a[1]), "r"(a[2]), "r"(a[3]),
          "r"(b[0]), "r"(b[1]));
}

__device__ __forceinline__ void ldsm_x4(unsigned* r, unsigned saddr) {
    asm volatile(
        "ldmatrix.sync.aligned.m8n8.x4.shared.b16 {%0,%1,%2,%3}, [%4];"
        : "=r"(r[0]), "=r"(r[1]), "=r"(r[2]), "=r"(r[3]) : "r"(saddr));
}

// ---------------------------------------------------------------------------
// Dual GEMM, single-pass fp16 tensor cores, ldmatrix fragment loads.
// 256 threads (8 warps), BM=128, BN=64, warp tile m=16 x n=64, K=64.
// smem (fp16, pitch 72): As[128], Bs[64] rows — 27 KB -> 8 blocks/SM cap.
// Both outputs fp16. Grid x: [0, 2*Nc/64) -> first half Wl/Cl, rest Wr/Cr.
// ---------------------------------------------------------------------------
#define AP 72
__global__ __launch_bounds__(256)
void dual_gemm_fp16(const float* __restrict__ A,
                    const float* __restrict__ Wl, const float* __restrict__ bl,
                    const float* __restrict__ Wr, const float* __restrict__ br,
                    __half* __restrict__ Cl, __half* __restrict__ Cr,
                    int M, int Nc) {
    extern __shared__ __half smh[];
    __half* As = smh;               // [128][AP]
    __half* Bs = smh + 128 * AP;    // [64][AP]  as [n][k]

    const int tid  = threadIdx.x;
    const int warp = tid >> 5, lane = tid & 31;
    const int g = lane >> 2, c = lane & 3;
    const int row0 = blockIdx.y * 128;
    const int col0 = blockIdx.x * 64;

    const bool isL = (col0 < Nc);
    const float* W    = isL ? Wl : Wr;
    const float* bias = isL ? bl : br;
    __half* C = isL ? Cl : Cr;
    const int cofs = isL ? col0 : col0 - Nc;

    // A tile: 128 rows x 64 cols -> fp16, packed half2 stores
    #pragma unroll
    for (int i = 0; i < 8; i++) {
        int idx = tid + i * 256;
        int r = idx >> 4, c4 = (idx & 15) << 2;
        int row = row0 + r;
        float4 v = make_float4(0.f, 0.f, 0.f, 0.f);
        if (row < M)
            v = *reinterpret_cast<const float4*>(A + (size_t)row * 64 + c4);
        __half2* dst = reinterpret_cast<__half2*>(&As[r * AP + c4]);
        dst[0] = __floats2half2_rn(v.x, v.y);
        dst[1] = __floats2half2_rn(v.z, v.w);
    }
    // B tile: W[k][cofs..] -> Bs[n][k] transposed, fp16
    #pragma unroll
    for (int i = 0; i < 4; i++) {
        int idx = tid + i * 256;
        int k = idx >> 4, c4 = (idx & 15) << 2;
        float4 v = *reinterpret_cast<const float4*>(W + (size_t)k * Nc + cofs + c4);
        Bs[(c4 + 0) * AP + k] = __float2half_rn(v.x);
        Bs[(c4 + 1) * AP + k] = __float2half_rn(v.y);
        Bs[(c4 + 2) * AP + k] = __float2half_rn(v.z);
        Bs[(c4 + 3) * AP + k] = __float2half_rn(v.w);
    }
    __syncthreads();

    float acc[8][4];
    #pragma unroll
    for (int n = 0; n < 8; n++)
        #pragma unroll
        for (int j = 0; j < 4; j++) acc[n][j] = 0.f;

    const int wr = warp * 16;
    // ldmatrix lane->row mappings (validated in R12/R14)
    const int a_rsub = (((lane >> 3) & 1) << 3) + (lane & 7);   // m16k16 x4
    const int a_koff = (lane >> 4) << 3;
    const int b_rsub = ((lane >> 4) << 3) + (lane & 7);          // n16k16 x4
    const int b_koff = ((lane >> 3) & 1) << 3;

    #pragma unroll
    for (int kk = 0; kk < 4; kk++) {
        const int k0 = kk * 16;
        unsigned a4[4];
        {
            int row = wr + a_rsub;
            unsigned sa = (unsigned)__cvta_generic_to_shared(&As[row * AP + k0 + a_koff]);
            ldsm_x4(a4, sa);
        }
        #pragma unroll
        for (int np = 0; np < 4; np++) {          // 4 n-pairs, 2 n8-tiles each
            int nrow = np * 16 + b_rsub;
            unsigned sb = (unsigned)__cvta_generic_to_shared(&Bs[nrow * AP + k0 + b_koff]);
            unsigned b4[4];
            ldsm_x4(b4, sb);
            #pragma unroll
            for (int sub = 0; sub < 2; sub++) {
                int n = np * 2 + sub;
                unsigned bb[2] = {b4[2 * sub], b4[2 * sub + 1]};
                mma_fp16(acc[n], a4, bb);
            }
        }
    }

    #pragma unroll
    for (int n = 0; n < 8; n++) {
        int colg = cofs + n * 8 + 2 * c;
        float bx = __ldg(bias + colg);
        float by = __ldg(bias + colg + 1);
        int r1 = row0 + wr + g, r2 = r1 + 8;
        if (r1 < M)
            *reinterpret_cast<__half2*>(C + (size_t)r1 * Nc + colg) =
                __floats2half2_rn(acc[n][0] + bx, acc[n][1] + by);
        if (r2 < M)
            *reinterpret_cast<__half2*>(C + (size_t)r2 * Nc + colg) =
                __floats2half2_rn(acc[n][2] + bx, acc[n][3] + by);
    }
}

// ---------------------------------------------------------------------------
// fp16 vector load
// ---------------------------------------------------------------------------
template<int PE>
__device__ __forceinline__ void loadVecH(const __half* __restrict__ p, float* v) {
    if constexpr (PE == 8) {
        uint4 t = __ldg(reinterpret_cast<const uint4*>(p));
        float2 f;
        f = __half22float2(*reinterpret_cast<__half2*>(&t.x)); v[0] = f.x; v[1] = f.y;
        f = __half22float2(*reinterpret_cast<__half2*>(&t.y)); v[2] = f.x; v[3] = f.y;
        f = __half22float2(*reinterpret_cast<__half2*>(&t.z)); v[4] = f.x; v[5] = f.y;
        f = __half22float2(*reinterpret_cast<__half2*>(&t.w)); v[6] = f.x; v[7] = f.y;
    } else {
        unsigned t = __ldg(reinterpret_cast<const unsigned*>(p));
        float2 f = __half22float2(*reinterpret_cast<__half2*>(&t));
        v[0] = f.x; v[1] = f.y;
    }
}

// ---------------------------------------------------------------------------
// Fused GATv2 edge pass (proven): warp per dst node, slot segments,
// no-max softmax + lrelu-identity dot, xl/xr fp16, math fp32.
// MEAN kernel re-zeros g_deg[w] for the next graph replay.
// ---------------------------------------------------------------------------
template<int CC, bool MEAN>
__global__ void fused_gat_kernel(const float* __restrict__ att,
                                 const float* __restrict__ bo,
                                 float* __restrict__ outp, int Nn) {
    constexpr int D = HEADS * CC;
    constexpr int PE = D / 32;
    int w = (blockIdx.x * blockDim.x + threadIdx.x) >> 5;
    int lane = threadIdx.x & 31;
    if (w >= Nn) return;

    const __half* xlh = reinterpret_cast<const __half*>(g_xlh_raw);
    const __half* xrh = reinterpret_cast<const __half*>(g_xrh_raw);
    const int f0 = lane * PE;

    int deg = g_deg[w];
    int cnt = (deg < SLOT_CAP) ? deg : SLOT_CAP;
    const int* seg = g_slots + (size_t)w * SLOT_CAP;

    float vr[PE], av6[PE], av4[PE];
    loadVecH<PE>(xrh + (size_t)w * D + f0, vr);
    #pragma unroll
    for (int j = 0; j < PE; j++) {
        float a = __ldg(att + f0 + j);
        av6[j] = (0.5f + 0.5f * NEG_SLOPE) * a;
        av4[j] = (0.5f - 0.5f * NEG_SLOPE) * a;
    }

    float l = 0.f;
    float acc[PE];
    #pragma unroll
    for (int j = 0; j < PE; j++) acc[j] = 0.f;

    float vl[PE];
    {
        int s0 = __ldg(seg);
        loadVecH<PE>(xlh + (size_t)s0 * D + f0, vl);
    }

    for (int p = 0; p < cnt; p++) {
        float cvl[PE];
        #pragma unroll
        for (int j = 0; j < PE; j++) cvl[j] = vl[j];
        if (p + 1 < cnt) {
            int sn = __ldg(seg + p + 1);
            loadVecH<PE>(xlh + (size_t)sn * D + f0, vl);
        }
        float partial = 0.f;
        #pragma unroll
        for (int j = 0; j < PE; j++) {
            float v = cvl[j] + vr[j];
            partial = fmaf(av6[j], v, partial);
            partial = fmaf(av4[j], fabsf(v), partial);
        }
        #pragma unroll
        for (int off = 4; off; off >>= 1)
            partial += __shfl_xor_sync(0xffffffffu, partial, off);

        float pe = __expf(partial);
        l += pe;
        #pragma unroll
        for (int j = 0; j < PE; j++)
            acc[j] = fmaf(pe, cvl[j], acc[j]);
    }

    if constexpr (MEAN) {
        if (lane == 0) g_deg[w] = 0;
    }

    float inv = 1.f / (l + 1e-16f);

    if constexpr (!MEAN) {
        float2 o;
        o.x = acc[0] * inv + __ldg(bo + f0 + 0);
        o.y = acc[1] * inv + __ldg(bo + f0 + 1);
        o.x = (o.x > 0.f) ? o.x : 0.f;
        o.y = (o.y > 0.f) ? o.y : 0.f;
        *reinterpret_cast<float2*>(outp + (size_t)w * D + f0) = o;
    } else {
        #pragma unroll
        for (int j = 0; j < PE; j++) acc[j] *= inv;
        #pragma unroll
        for (int j = 0; j < PE; j++) {
            acc[j] += __shfl_xor_sync(0xffffffffu, acc[j], 8);
            acc[j] += __shfl_xor_sync(0xffffffffu, acc[j], 16);
        }
        if (lane < 8) {
            float o[PE];
            #pragma unroll
            for (int j = 0; j < PE; j++) {
                float v = 0.25f * acc[j] + __ldg(bo + f0 + j);
                o[j] = (v > 0.f) ? v : 0.f;
            }
            #pragma unroll
            for (int j = 0; j < PE / 4; j++)
                *reinterpret_cast<float4*>(outp + (size_t)w * 64 + f0 + j * 4) =
                    make_float4(o[j*4], o[j*4+1], o[j*4+2], o[j*4+3]);
        }
    }
}

// ---------------------------------------------------------------------------
// Host launcher — 5 kernels total
// ---------------------------------------------------------------------------
extern "C" void kernel_launch(void* const* d_in, const int* in_sizes, int n_in,
                              void* d_out, int out_size) {
    const float* x   = (const float*)d_in[0];
    const void*  ei  = d_in[1];
    const float* Wl1 = (const float*)d_in[3];
    const float* bl1 = (const float*)d_in[4];
    const float* Wr1 = (const float*)d_in[5];
    const float* br1 = (const float*)d_in[6];
    const float* att1= (const float*)d_in[7];
    const float* bo1 = (const float*)d_in[8];
    const float* Wl2 = (const float*)d_in[9];
    const float* bl2 = (const float*)d_in[10];
    const float* Wr2 = (const float*)d_in[11];
    const float* br2 = (const float*)d_in[12];
    const float* att2= (const float*)d_in[13];
    const float* bo2 = (const float*)d_in[14];
    float* out = (float*)d_out;

    const int N = in_sizes[0] / 64;
    const int E = in_sizes[1] / 2;

    __half* p_xlh; __half* p_xrh; float* p_h;
    cudaGetSymbolAddress((void**)&p_xlh, g_xlh_raw);
    cudaGetSymbolAddress((void**)&p_xrh, g_xrh_raw);
    cudaGetSymbolAddress((void**)&p_h,   g_h);

    const int TB = 256;
    const int SMEM_GEMM = (128 + 64) * AP * 2;   // 27648 B
    static int attrSet = 0;
    if (!attrSet) {
        cudaFuncSetAttribute(dual_gemm_fp16,
                             cudaFuncAttributeMaxDynamicSharedMemorySize, SMEM_GEMM);
        attrSet = 1;
    }

    int fusedBlocks = cdiv(N, TB / 32);

    // ---- edge grouping ----
    fill_kernel<<<cdiv(E + N, TB), TB>>>(ei, E, N);

    // ---- layer 1: dual GEMM (Nc=64) + fused GAT ----
    dim3 g1(2, cdiv(N, 128));
    dual_gemm_fp16<<<g1, TB, SMEM_GEMM>>>(x, Wl1, bl1, Wr1, br1, p_xlh, p_xrh, N, 64);
    fused_gat_kernel<16, false><<<fusedBlocks, TB>>>(att1, bo1, p_h, N);

    // ---- layer 2: dual GEMM (Nc=256) + fused GAT (zeros g_deg) ----
    dim3 g2(8, cdiv(N, 128));
    dual_gemm_fp16<<<g2, TB, SMEM_GEMM>>>(p_h, Wl2, bl2, Wr2, br2, p_xlh, p_xrh, N, 256);
    fused_gat_kernel<64, true><<<fusedBlocks, TB>>>(att2, bo2, out, N);
}